// round 13
// baseline (speedup 1.0000x reference)
#include <cuda_runtime.h>
#include <cuda_bf16.h>

// Problem constants
#define NC 4
#define NN 512
#define ED 512
#define PD 64
#define NH 32
#define HD 16

// wbs row stride: 40 -> B-fragment bank = (8*lc + 8*nc + lr) mod 32, conflict-free
#define WS 40

// f32x2 packed-math helpers (sm_100+)
#define FMA2(acc, a, b) asm("fma.rn.f32x2 %0, %1, %2, %0;" : "+l"(acc) : "l"(a), "l"(b))
#define MUL2(d, a, b)   asm("mul.rn.f32x2 %0, %1, %2;" : "=l"(d) : "l"(a), "l"(b))
#define PACK2(d, x)     asm("mov.b64 %0, {%1, %1};" : "=l"(d) : "f"(x))
#define UNPACK2(lo, hi, v) asm("mov.b64 {%0, %1}, %2;" : "=f"(lo), "=f"(hi) : "l"(v))

#define CVT_TF32(u, f) asm("cvt.rna.tf32.f32 %0, %1;" : "=r"(u) : "f"(f))

__device__ __forceinline__ void mma_tf32(float& d0, float& d1, float& d2, float& d3,
                                         unsigned a0, unsigned a1, unsigned a2, unsigned a3,
                                         unsigned b0, unsigned b1) {
    asm volatile("mma.sync.aligned.m16n8k8.row.col.f32.tf32.tf32.f32 "
                 "{%0,%1,%2,%3}, {%4,%5,%6,%7}, {%8,%9}, {%0,%1,%2,%3};"
                 : "+f"(d0), "+f"(d1), "+f"(d2), "+f"(d3)
                 : "r"(a0), "r"(a1), "r"(a2), "r"(a3), "r"(b0), "r"(b1));
}

// Scratch (static device arrays; no allocations allowed)
__device__ float g_xq[NC * NN * ED];
__device__ float g_q [NC * NN * ED];
__device__ float g_k [NC * NN * ED];
__device__ float g_v [NC * NN * ED];
__device__ float g_vf[NC * NN * NH];                 // [c, j, h]
__device__ float g_bias[(size_t)NC * NN * NN * NH];  // [c, i, j, h]

// ---------------------------------------------------------------------------
// Kernel A: LayerNorm(query) -> g_xq.
// ---------------------------------------------------------------------------
__global__ void ln_q_kernel(const float* __restrict__ x,
                            const float* __restrict__ g,
                            const float* __restrict__ b) {
    int row = blockIdx.x;
    const float* xr = x + (size_t)row * ED;
    float* o = g_xq + (size_t)row * ED;
    int tid = threadIdx.x;  // 128
    float v[4];
    float s = 0.f, s2 = 0.f;
#pragma unroll
    for (int t = 0; t < 4; t++) {
        float vv = xr[tid + t * 128];
        v[t] = vv; s += vv; s2 += vv * vv;
    }
#pragma unroll
    for (int off = 16; off; off >>= 1) {
        s  += __shfl_down_sync(0xffffffffu, s,  off);
        s2 += __shfl_down_sync(0xffffffffu, s2, off);
    }
    __shared__ float sh[8];
    if ((tid & 31) == 0) { sh[tid >> 5] = s; sh[4 + (tid >> 5)] = s2; }
    __syncthreads();
    float S  = sh[0] + sh[1] + sh[2] + sh[3];
    float S2 = sh[4] + sh[5] + sh[6] + sh[7];
    float mu   = S * (1.f / ED);
    float var  = S2 * (1.f / ED) - mu * mu;
    float rstd = rsqrtf(var + 1e-5f);
#pragma unroll
    for (int t = 0; t < 4; t++) {
        int e = tid + t * 128;
        o[e] = (v[t] - mu) * rstd * g[e] + b[e];
    }
}

// ---------------------------------------------------------------------------
// Kernel B: QKV projection GEMM (f32x2 packed).
// ---------------------------------------------------------------------------
__global__ void __launch_bounds__(256) qkv_gemm(
    const float* __restrict__ Wq, const float* __restrict__ Wk,
    const float* __restrict__ Wv) {
    const float* W; float* O; float scale = 1.f;
    if (blockIdx.z == 0)      { W = Wq; O = g_q; scale = 0.25f; }
    else if (blockIdx.z == 1) { W = Wk; O = g_k; }
    else                      { W = Wv; O = g_v; }
    const float* A = g_xq;

    __shared__ float As[16][68];
    __shared__ float Bs[16][68];
    int tid = threadIdx.x;
    int tx = tid & 15, ty = tid >> 4;
    int m0 = blockIdx.y * 64, n0 = blockIdx.x * 64;
    unsigned long long acc[4][2];
#pragma unroll
    for (int i = 0; i < 4; i++) { acc[i][0] = 0ull; acc[i][1] = 0ull; }
    int lr = tid >> 2;
    int lk = (tid & 3) * 4;

    for (int k0 = 0; k0 < ED; k0 += 16) {
        float4 av = *(const float4*)&A[(size_t)(m0 + lr) * ED + k0 + lk];
        float4 bv = *(const float4*)&W[(size_t)(n0 + lr) * ED + k0 + lk];
        As[lk + 0][lr] = av.x; As[lk + 1][lr] = av.y;
        As[lk + 2][lr] = av.z; As[lk + 3][lr] = av.w;
        Bs[lk + 0][lr] = bv.x; Bs[lk + 1][lr] = bv.y;
        Bs[lk + 2][lr] = bv.z; Bs[lk + 3][lr] = bv.w;
        __syncthreads();
#pragma unroll
        for (int kk = 0; kk < 16; kk++) {
            float4 ar = *(const float4*)&As[kk][ty * 4];
            ulonglong2 br = *(const ulonglong2*)&Bs[kk][tx * 4];
            unsigned long long a0, a1, a2, a3;
            PACK2(a0, ar.x); PACK2(a1, ar.y); PACK2(a2, ar.z); PACK2(a3, ar.w);
            FMA2(acc[0][0], a0, br.x); FMA2(acc[0][1], a0, br.y);
            FMA2(acc[1][0], a1, br.x); FMA2(acc[1][1], a1, br.y);
            FMA2(acc[2][0], a2, br.x); FMA2(acc[2][1], a2, br.y);
            FMA2(acc[3][0], a3, br.x); FMA2(acc[3][1], a3, br.y);
        }
        __syncthreads();
    }
#pragma unroll
    for (int i = 0; i < 4; i++) {
        float4 o; float lo, hi;
        UNPACK2(lo, hi, acc[i][0]); o.x = lo * scale; o.y = hi * scale;
        UNPACK2(lo, hi, acc[i][1]); o.z = lo * scale; o.w = hi * scale;
        *(float4*)&O[(size_t)(m0 + ty * 4 + i) * ED + n0 + tx * 4] = o;
    }
}

// ---------------------------------------------------------------------------
// Kernel C: vf[c,j,h] = sum_d v[c,j,h*16+d] * Wf[h*16+d]
// ---------------------------------------------------------------------------
__global__ void vf_kernel(const float* __restrict__ Wf) {
    int idx = blockIdx.x * blockDim.x + threadIdx.x;
    int h = idx & 31;
    int cj = idx >> 5;
    const float* vr = g_v + (size_t)cj * ED + h * HD;
    const float* wf = Wf + h * HD;
    float s = 0.f;
#pragma unroll
    for (int d = 0; d < HD; d++) s += vr[d] * wf[d];
    g_vf[(size_t)cj * NH + h] = s;
}

// ---------------------------------------------------------------------------
// Kernel E: bias GEMM on tensor cores, LN folded into epilogue.
//   bias[m][h] = rstd_m * (pair_raw[m]·W'[h] - mu_m * s_h) + c1_h
//   W' = lnpg∘Wb,  s_h = sum_k W'[k][h],  c1_h = lnpb·Wb[h] + bb[h]
// Byte-identical to R12; host sets max shared-memory carveout so 4 blocks
// (4 x 46.3 KB = 185 KB < 228 KB) fit per SM instead of 2.
// ---------------------------------------------------------------------------
#define BM 128
__global__ void __launch_bounds__(256) bias_kernel(
    const float* __restrict__ pair, const float* __restrict__ lnpg,
    const float* __restrict__ lnpb, const float* __restrict__ Wb,
    const float* __restrict__ bb) {
    __shared__ float pt[BM * 68];     // RAW pair tile (fp32)
    __shared__ float wbs[64 * WS];    // wbs[k*WS+n] = lnpg[k] * Wb[n][k]
    __shared__ float mus[BM], rstds[BM];
    __shared__ float ssm[NH], c1sm[NH];
    int tid = threadIdx.x;
    size_t rowbase = (size_t)blockIdx.x * BM;

    // load pair tile (coalesced)
    const float4* src = (const float4*)(pair + rowbase * PD);
#pragma unroll
    for (int t = 0; t < 8; t++) {
        int idx = tid + t * 256;
        int row = idx >> 4, f4 = idx & 15;
        float4 v = src[idx];
        *(float4*)&pt[row * 68 + f4 * 4] = v;
    }
    // W' = lnpg * Wb, transposed into smem
    for (int idx = tid; idx < 2048; idx += 256) {
        int n = idx >> 6, k = idx & 63;
        wbs[k * WS + n] = lnpg[k] * Wb[idx];
    }
    __syncthreads();

    // Row statistics only (no write-back): 2 threads per row
    {
        int row = tid >> 1, half = tid & 1;
        const float* pr = pt + row * 68 + half * 32;
        float s = 0.f, s2 = 0.f;
#pragma unroll
        for (int t = 0; t < 8; t++) {
            float4 v = *(const float4*)&pr[t * 4];
            s  += v.x + v.y + v.z + v.w;
            s2 += v.x * v.x + v.y * v.y + v.z * v.z + v.w * v.w;
        }
        s  += __shfl_xor_sync(0xffffffffu, s, 1);
        s2 += __shfl_xor_sync(0xffffffffu, s2, 1);
        if (half == 0) {
            float mu  = s * (1.f / PD);
            float var = s2 * (1.f / PD) - mu * mu;
            mus[row]   = mu;
            rstds[row] = rsqrtf(var + 1e-5f);
        }
    }
    // s_h, c1_h: h = tid>>3 (0..31), kq = tid&7; shfl-reduce in 8-groups
    {
        int h = tid >> 3, kq = tid & 7;
        float sv = 0.f, c1 = 0.f;
#pragma unroll
        for (int t = 0; t < 8; t++) {
            int k = kq * 8 + t;
            sv += wbs[k * WS + h];
            c1 += lnpb[k] * Wb[h * PD + k];
        }
#pragma unroll
        for (int off = 1; off < 8; off <<= 1) {
            sv += __shfl_xor_sync(0xffffffffu, sv, off, 8);
            c1 += __shfl_xor_sync(0xffffffffu, c1, off, 8);
        }
        if (kq == 0) { ssm[h] = sv; c1sm[h] = c1 + bb[h]; }
    }
    __syncthreads();

    // Tensor-core GEMM on RAW pair tile (R4-proven fragment layout)
    int w = tid >> 5, lane = tid & 31;
    int lr = lane >> 2, lc = lane & 3;
    int arow0 = w * 16 + lr;

    float d[4][4];
#pragma unroll
    for (int nc = 0; nc < 4; nc++)
        d[nc][0] = d[nc][1] = d[nc][2] = d[nc][3] = 0.f;

#pragma unroll
    for (int kc = 0; kc < 8; kc++) {
        float af[4];
        af[0] = pt[arow0 * 68 + kc * 8 + lc];
        af[1] = pt[(arow0 + 8) * 68 + kc * 8 + lc];
        af[2] = pt[arow0 * 68 + kc * 8 + lc + 4];
        af[3] = pt[(arow0 + 8) * 68 + kc * 8 + lc + 4];
        unsigned ah[4], al[4];
#pragma unroll
        for (int t = 0; t < 4; t++) {
            CVT_TF32(ah[t], af[t]);
            float res = af[t] - __uint_as_float(ah[t]);
            CVT_TF32(al[t], res);
        }
#pragma unroll
        for (int nc = 0; nc < 4; nc++) {
            float bf0 = wbs[(kc * 8 + lc) * WS + nc * 8 + lr];
            float bf1 = wbs[(kc * 8 + lc + 4) * WS + nc * 8 + lr];
            unsigned bh0, bh1, bl0, bl1;
            CVT_TF32(bh0, bf0);
            CVT_TF32(bh1, bf1);
            float r0 = bf0 - __uint_as_float(bh0);
            float r1 = bf1 - __uint_as_float(bh1);
            CVT_TF32(bl0, r0);
            CVT_TF32(bl1, r1);
            mma_tf32(d[nc][0], d[nc][1], d[nc][2], d[nc][3],
                     ah[0], ah[1], ah[2], ah[3], bh0, bh1);
            mma_tf32(d[nc][0], d[nc][1], d[nc][2], d[nc][3],
                     ah[0], ah[1], ah[2], ah[3], bl0, bl1);
            mma_tf32(d[nc][0], d[nc][1], d[nc][2], d[nc][3],
                     al[0], al[1], al[2], al[3], bh0, bh1);
        }
    }

    // epilogue: folded LN + constants
    float mu0 = mus[arow0],     rs0 = rstds[arow0];
    float mu1 = mus[arow0 + 8], rs1 = rstds[arow0 + 8];
    size_t row = rowbase + arow0;
#pragma unroll
    for (int nc = 0; nc < 4; nc++) {
        int col = nc * 8 + 2 * lc;
        float s0 = ssm[col], s1 = ssm[col + 1];
        float c0 = c1sm[col], c1v = c1sm[col + 1];
        float2 o0, o1;
        o0.x = rs0 * (d[nc][0] - mu0 * s0) + c0;
        o0.y = rs0 * (d[nc][1] - mu0 * s1) + c1v;
        o1.x = rs1 * (d[nc][2] - mu1 * s0) + c0;
        o1.y = rs1 * (d[nc][3] - mu1 * s1) + c1v;
        *(float2*)&g_bias[row * NH + col]       = o0;
        *(float2*)&g_bias[(row + 8) * NH + col] = o1;
    }
}

// ---------------------------------------------------------------------------
// Kernel F: streaming attention + force (EXACT R8-proven version).
// 256 threads = 8 warps; lane = head h, warp w covers j == w (mod 8).
// ---------------------------------------------------------------------------
__global__ void __launch_bounds__(256, 2) attn_kernel(
    const float* __restrict__ delta, float* __restrict__ out) {
    int c = blockIdx.y;
    int ibase = blockIdx.x * 4;
    int tid = threadIdx.x;
    int w = tid >> 5, h = tid & 31;

    ulonglong2 q[4][4];
#pragma unroll
    for (int ii = 0; ii < 4; ii++) {
        const float* qp = g_q + ((size_t)(c * NN) + ibase + ii) * ED + h * HD;
#pragma unroll
        for (int t = 0; t < 4; t++)
            q[ii][t] = *(const ulonglong2*)(qp + t * 4);
    }

    float l[4]  = {0.f, 0.f, 0.f, 0.f};
    float n0[4] = {0.f, 0.f, 0.f, 0.f};
    float n1[4] = {0.f, 0.f, 0.f, 0.f};
    float n2[4] = {0.f, 0.f, 0.f, 0.f};

    const size_t cb = (size_t)(c * NN) + ibase;
#pragma unroll 2
    for (int j = w; j < NN; j += 8) {
        const float* kp = g_k + ((size_t)(c * NN) + j) * ED + h * HD;
        ulonglong2 k0 = *(const ulonglong2*)(kp + 0);
        ulonglong2 k1 = *(const ulonglong2*)(kp + 4);
        ulonglong2 k2 = *(const ulonglong2*)(kp + 8);
        ulonglong2 k3 = *(const ulonglong2*)(kp + 12);
        float vfv = g_vf[((size_t)(c * NN) + j) * NH + h];
        const float* dp = delta + (cb * NN + j) * 3;
        const float* bp = g_bias + (cb * NN + j) * NH + h;
#pragma unroll
        for (int ii = 0; ii < 4; ii++) {
            unsigned long long a;
            MUL2(a, q[ii][0].x, k0.x);
            FMA2(a, q[ii][0].y, k0.y);
            FMA2(a, q[ii][1].x, k1.x);
            FMA2(a, q[ii][1].y, k1.y);
            FMA2(a, q[ii][2].x, k2.x);
            FMA2(a, q[ii][2].y, k2.y);
            FMA2(a, q[ii][3].x, k3.x);
            FMA2(a, q[ii][3].y, k3.y);
            float lo, hi; UNPACK2(lo, hi, a);
            float z = lo + hi + bp[(size_t)ii * (NN * NH)];
            float we = __expf(z);
            float wv = we * vfv;
            float d0 = dp[ii * (NN * 3) + 0];
            float d1 = dp[ii * (NN * 3) + 1];
            float d2 = dp[ii * (NN * 3) + 2];
            l[ii]  += we;
            n0[ii] += wv * d0;
            n1[ii] += wv * d1;
            n2[ii] += wv * d2;
        }
    }

    __shared__ float ms[8][4][32][4];
#pragma unroll
    for (int ii = 0; ii < 4; ii++)
        *(float4*)&ms[w][ii][h][0] = make_float4(l[ii], n0[ii], n1[ii], n2[ii]);
    __syncthreads();

    if (w < 4) {
        int ii = w;
        float L = 0.f, F0 = 0.f, F1 = 0.f, F2 = 0.f;
#pragma unroll
        for (int ww = 0; ww < 8; ww++) {
            float4 a = *(const float4*)&ms[ww][ii][h][0];
            L += a.x; F0 += a.y; F1 += a.z; F2 += a.w;
        }
        // per-(i, head) normalization BEFORE summing over heads
        float inv = 1.f / L;
        F0 *= inv; F1 *= inv; F2 *= inv;
#pragma unroll
        for (int off = 16; off; off >>= 1) {
            F0 += __shfl_down_sync(0xffffffffu, F0, off);
            F1 += __shfl_down_sync(0xffffffffu, F1, off);
            F2 += __shfl_down_sync(0xffffffffu, F2, off);
        }
        if (h == 0) {
            float* op = out + ((size_t)(c * NN) + ibase + ii) * 3;
            op[0] = F0; op[1] = F1; op[2] = F2;
        }
    }
}

// ---------------------------------------------------------------------------
// Host launch
// ---------------------------------------------------------------------------
extern "C" void kernel_launch(void* const* d_in, const int* in_sizes, int n_in,
                              void* d_out, int out_size) {
    const float* query = (const float*)d_in[0];
    const float* pair  = (const float*)d_in[1];
    const float* delta = (const float*)d_in[2];
    const float* lnqg  = (const float*)d_in[3];
    const float* lnqb  = (const float*)d_in[4];
    const float* lnpg  = (const float*)d_in[5];
    const float* lnpb  = (const float*)d_in[6];
    const float* Wq    = (const float*)d_in[7];
    const float* Wk    = (const float*)d_in[8];
    const float* Wv    = (const float*)d_in[9];
    const float* Wb    = (const float*)d_in[10];
    const float* bb    = (const float*)d_in[11];
    const float* Wf    = (const float*)d_in[12];
    float* out = (float*)d_out;

    // Max shared-memory carveout so 4 x 46.3 KB bias blocks fit per SM.
    static int carveout_done = 0;
    if (!carveout_done) {
        cudaFuncSetAttribute(bias_kernel,
                             cudaFuncAttributePreferredSharedMemoryCarveout, 100);
        carveout_done = 1;
    }

    ln_q_kernel<<<NC * NN, 128>>>(query, lnqg, lnqb);

    dim3 gg(ED / 64, (NC * NN) / 64, 3);
    qkv_gemm<<<gg, 256>>>(Wq, Wk, Wv);

    vf_kernel<<<(NC * NN * NH) / 256, 256>>>(Wf);

    bias_kernel<<<(NC * NN * NN) / BM, 256>>>(pair, lnpg, lnpb, Wb, bb);

    attn_kernel<<<dim3(NN / 4, NC), 256>>>(delta, out);
}

// round 14
// speedup vs baseline: 1.1309x; 1.1309x over previous
#include <cuda_runtime.h>
#include <cuda_bf16.h>

// Problem constants
#define NC 4
#define NN 512
#define ED 512
#define PD 64
#define NH 32
#define HD 16

// wbs row stride: 40 -> B-fragment bank conflict-free (bias kernel)
#define WS 40

// f32x2 packed-math helpers (sm_100+)
#define FMA2(acc, a, b) asm("fma.rn.f32x2 %0, %1, %2, %0;" : "+l"(acc) : "l"(a), "l"(b))
#define MUL2(d, a, b)   asm("mul.rn.f32x2 %0, %1, %2;" : "=l"(d) : "l"(a), "l"(b))
#define PACK2(d, x)     asm("mov.b64 %0, {%1, %1};" : "=l"(d) : "f"(x))
#define UNPACK2(lo, hi, v) asm("mov.b64 {%0, %1}, %2;" : "=f"(lo), "=f"(hi) : "l"(v))

#define CVT_TF32(u, f) asm("cvt.rna.tf32.f32 %0, %1;" : "=r"(u) : "f"(f))

__device__ __forceinline__ void mma_tf32(float& d0, float& d1, float& d2, float& d3,
                                         unsigned a0, unsigned a1, unsigned a2, unsigned a3,
                                         unsigned b0, unsigned b1) {
    asm volatile("mma.sync.aligned.m16n8k8.row.col.f32.tf32.tf32.f32 "
                 "{%0,%1,%2,%3}, {%4,%5,%6,%7}, {%8,%9}, {%0,%1,%2,%3};"
                 : "+f"(d0), "+f"(d1), "+f"(d2), "+f"(d3)
                 : "r"(a0), "r"(a1), "r"(a2), "r"(a3), "r"(b0), "r"(b1));
}

// Scratch (static device arrays; no allocations allowed)
__device__ float g_xq[NC * NN * ED];
__device__ float g_q [NC * NN * ED];
__device__ float g_k [NC * NN * ED];
__device__ float g_v [NC * NN * ED];
__device__ float g_vf[NC * NN * NH];                 // [c, j, h]
__device__ float g_bias[(size_t)NC * NN * NN * NH];  // [c, i, j, h]

// ---------------------------------------------------------------------------
// Kernel A: LayerNorm(query) -> g_xq.
// ---------------------------------------------------------------------------
__global__ void ln_q_kernel(const float* __restrict__ x,
                            const float* __restrict__ g,
                            const float* __restrict__ b) {
    int row = blockIdx.x;
    const float* xr = x + (size_t)row * ED;
    float* o = g_xq + (size_t)row * ED;
    int tid = threadIdx.x;  // 128
    float v[4];
    float s = 0.f, s2 = 0.f;
#pragma unroll
    for (int t = 0; t < 4; t++) {
        float vv = xr[tid + t * 128];
        v[t] = vv; s += vv; s2 += vv * vv;
    }
#pragma unroll
    for (int off = 16; off; off >>= 1) {
        s  += __shfl_down_sync(0xffffffffu, s,  off);
        s2 += __shfl_down_sync(0xffffffffu, s2, off);
    }
    __shared__ float sh[8];
    if ((tid & 31) == 0) { sh[tid >> 5] = s; sh[4 + (tid >> 5)] = s2; }
    __syncthreads();
    float S  = sh[0] + sh[1] + sh[2] + sh[3];
    float S2 = sh[4] + sh[5] + sh[6] + sh[7];
    float mu   = S * (1.f / ED);
    float var  = S2 * (1.f / ED) - mu * mu;
    float rstd = rsqrtf(var + 1e-5f);
#pragma unroll
    for (int t = 0; t < 4; t++) {
        int e = tid + t * 128;
        o[e] = (v[t] - mu) * rstd * g[e] + b[e];
    }
}

// ---------------------------------------------------------------------------
// Kernel B: QKV projection GEMM on tensor cores (tf32 3-mma split).
// O[m][n] = sum_k xq[m][k] * W[n][k], M=2048, N=512, K=512.
// Block: 128x64 tile, BK=16, 256 threads / 8 warps (warp = m16 strip, all 64 n).
// hi/lo tf32 split PRE-COMPUTED into smem at tile-load time -> mainloop has
// zero CVT.  Fragment addressing identical to the proven bias kernel.
// Stride 20: A-frag bank = (20*lr + lc) distinct; B-frag same pattern.
// ---------------------------------------------------------------------------
#define QBK 16
__global__ void __launch_bounds__(256) qkv_gemm_tc(
    const float* __restrict__ Wq, const float* __restrict__ Wk,
    const float* __restrict__ Wv) {
    const float* W; float* O; float scale = 1.f;
    if (blockIdx.z == 0)      { W = Wq; O = g_q; scale = 0.25f; }
    else if (blockIdx.z == 1) { W = Wk; O = g_k; }
    else                      { W = Wv; O = g_v; }
    const float* A = g_xq;

    __shared__ float Ahi[128 * 20], Alo[128 * 20];   // [m][k] tf32 hi/lo
    __shared__ float Bhi[64 * 20],  Blo[64 * 20];    // [n][k] tf32 hi/lo

    int tid = threadIdx.x;
    int m0 = blockIdx.y * 128, n0 = blockIdx.x * 64;
    int w = tid >> 5, lane = tid & 31;
    int lr = lane >> 2, lc = lane & 3;
    int arow0 = w * 16 + lr;

    float d[8][4];
#pragma unroll
    for (int nc = 0; nc < 8; nc++)
        d[nc][0] = d[nc][1] = d[nc][2] = d[nc][3] = 0.f;

    for (int k0 = 0; k0 < ED; k0 += QBK) {
        __syncthreads();   // previous iteration's MMAs done reading tiles
        // A tile: 128 rows x 16 k = 512 float4, 2 per thread
#pragma unroll
        for (int t = 0; t < 2; t++) {
            int idx = tid + t * 256;
            int row = idx >> 2, f4 = idx & 3;
            float4 v = *(const float4*)&A[(size_t)(m0 + row) * ED + k0 + f4 * 4];
            float4 hi4, lo4;
            unsigned u;
            CVT_TF32(u, v.x); hi4.x = __uint_as_float(u); { float r = v.x - hi4.x; CVT_TF32(u, r); lo4.x = __uint_as_float(u); }
            CVT_TF32(u, v.y); hi4.y = __uint_as_float(u); { float r = v.y - hi4.y; CVT_TF32(u, r); lo4.y = __uint_as_float(u); }
            CVT_TF32(u, v.z); hi4.z = __uint_as_float(u); { float r = v.z - hi4.z; CVT_TF32(u, r); lo4.z = __uint_as_float(u); }
            CVT_TF32(u, v.w); hi4.w = __uint_as_float(u); { float r = v.w - hi4.w; CVT_TF32(u, r); lo4.w = __uint_as_float(u); }
            *(float4*)&Ahi[row * 20 + f4 * 4] = hi4;
            *(float4*)&Alo[row * 20 + f4 * 4] = lo4;
        }
        // B tile: 64 rows x 16 k = 256 float4, 1 per thread
        {
            int row = tid >> 2, f4 = tid & 3;
            float4 v = *(const float4*)&W[(size_t)(n0 + row) * ED + k0 + f4 * 4];
            float4 hi4, lo4;
            unsigned u;
            CVT_TF32(u, v.x); hi4.x = __uint_as_float(u); { float r = v.x - hi4.x; CVT_TF32(u, r); lo4.x = __uint_as_float(u); }
            CVT_TF32(u, v.y); hi4.y = __uint_as_float(u); { float r = v.y - hi4.y; CVT_TF32(u, r); lo4.y = __uint_as_float(u); }
            CVT_TF32(u, v.z); hi4.z = __uint_as_float(u); { float r = v.z - hi4.z; CVT_TF32(u, r); lo4.z = __uint_as_float(u); }
            CVT_TF32(u, v.w); hi4.w = __uint_as_float(u); { float r = v.w - hi4.w; CVT_TF32(u, r); lo4.w = __uint_as_float(u); }
            *(float4*)&Bhi[row * 20 + f4 * 4] = hi4;
            *(float4*)&Blo[row * 20 + f4 * 4] = lo4;
        }
        __syncthreads();

#pragma unroll
        for (int kc = 0; kc < QBK / 8; kc++) {
            // A fragments (hi + lo), proven m16n8k8 row layout
            unsigned ah[4], al[4];
            ah[0] = __float_as_uint(Ahi[arow0 * 20 + kc * 8 + lc]);
            ah[1] = __float_as_uint(Ahi[(arow0 + 8) * 20 + kc * 8 + lc]);
            ah[2] = __float_as_uint(Ahi[arow0 * 20 + kc * 8 + lc + 4]);
            ah[3] = __float_as_uint(Ahi[(arow0 + 8) * 20 + kc * 8 + lc + 4]);
            al[0] = __float_as_uint(Alo[arow0 * 20 + kc * 8 + lc]);
            al[1] = __float_as_uint(Alo[(arow0 + 8) * 20 + kc * 8 + lc]);
            al[2] = __float_as_uint(Alo[arow0 * 20 + kc * 8 + lc + 4]);
            al[3] = __float_as_uint(Alo[(arow0 + 8) * 20 + kc * 8 + lc + 4]);
#pragma unroll
            for (int nc = 0; nc < 8; nc++) {
                int nrow = nc * 8 + lr;
                unsigned bh0 = __float_as_uint(Bhi[nrow * 20 + kc * 8 + lc]);
                unsigned bh1 = __float_as_uint(Bhi[nrow * 20 + kc * 8 + lc + 4]);
                unsigned bl0 = __float_as_uint(Blo[nrow * 20 + kc * 8 + lc]);
                unsigned bl1 = __float_as_uint(Blo[nrow * 20 + kc * 8 + lc + 4]);
                mma_tf32(d[nc][0], d[nc][1], d[nc][2], d[nc][3],
                         ah[0], ah[1], ah[2], ah[3], bh0, bh1);
                mma_tf32(d[nc][0], d[nc][1], d[nc][2], d[nc][3],
                         ah[0], ah[1], ah[2], ah[3], bl0, bl1);
                mma_tf32(d[nc][0], d[nc][1], d[nc][2], d[nc][3],
                         al[0], al[1], al[2], al[3], bh0, bh1);
            }
        }
    }

    // epilogue: proven C-fragment mapping, scaled
    size_t row = (size_t)(m0 + arow0);
#pragma unroll
    for (int nc = 0; nc < 8; nc++) {
        int col = n0 + nc * 8 + 2 * lc;
        *(float2*)&O[row * ED + col] =
            make_float2(d[nc][0] * scale, d[nc][1] * scale);
        *(float2*)&O[(row + 8) * ED + col] =
            make_float2(d[nc][2] * scale, d[nc][3] * scale);
    }
}

// ---------------------------------------------------------------------------
// Kernel C: vf[c,j,h] = sum_d v[c,j,h*16+d] * Wf[h*16+d]
// ---------------------------------------------------------------------------
__global__ void vf_kernel(const float* __restrict__ Wf) {
    int idx = blockIdx.x * blockDim.x + threadIdx.x;
    int h = idx & 31;
    int cj = idx >> 5;
    const float* vr = g_v + (size_t)cj * ED + h * HD;
    const float* wf = Wf + h * HD;
    float s = 0.f;
#pragma unroll
    for (int d = 0; d < HD; d++) s += vr[d] * wf[d];
    g_vf[(size_t)cj * NH + h] = s;
}

// ---------------------------------------------------------------------------
// Kernel E: bias GEMM on tensor cores, LN folded into epilogue (R12 exact;
// no carveout override — R13 showed it hurts).
// ---------------------------------------------------------------------------
#define BM 128
__global__ void __launch_bounds__(256) bias_kernel(
    const float* __restrict__ pair, const float* __restrict__ lnpg,
    const float* __restrict__ lnpb, const float* __restrict__ Wb,
    const float* __restrict__ bb) {
    __shared__ float pt[BM * 68];     // RAW pair tile (fp32)
    __shared__ float wbs[64 * WS];    // wbs[k*WS+n] = lnpg[k] * Wb[n][k]
    __shared__ float mus[BM], rstds[BM];
    __shared__ float ssm[NH], c1sm[NH];
    int tid = threadIdx.x;
    size_t rowbase = (size_t)blockIdx.x * BM;

    const float4* src = (const float4*)(pair + rowbase * PD);
#pragma unroll
    for (int t = 0; t < 8; t++) {
        int idx = tid + t * 256;
        int row = idx >> 4, f4 = idx & 15;
        float4 v = src[idx];
        *(float4*)&pt[row * 68 + f4 * 4] = v;
    }
    for (int idx = tid; idx < 2048; idx += 256) {
        int n = idx >> 6, k = idx & 63;
        wbs[k * WS + n] = lnpg[k] * Wb[idx];
    }
    __syncthreads();

    {
        int row = tid >> 1, half = tid & 1;
        const float* pr = pt + row * 68 + half * 32;
        float s = 0.f, s2 = 0.f;
#pragma unroll
        for (int t = 0; t < 8; t++) {
            float4 v = *(const float4*)&pr[t * 4];
            s  += v.x + v.y + v.z + v.w;
            s2 += v.x * v.x + v.y * v.y + v.z * v.z + v.w * v.w;
        }
        s  += __shfl_xor_sync(0xffffffffu, s, 1);
        s2 += __shfl_xor_sync(0xffffffffu, s2, 1);
        if (half == 0) {
            float mu  = s * (1.f / PD);
            float var = s2 * (1.f / PD) - mu * mu;
            mus[row]   = mu;
            rstds[row] = rsqrtf(var + 1e-5f);
        }
    }
    {
        int h = tid >> 3, kq = tid & 7;
        float sv = 0.f, c1 = 0.f;
#pragma unroll
        for (int t = 0; t < 8; t++) {
            int k = kq * 8 + t;
            sv += wbs[k * WS + h];
            c1 += lnpb[k] * Wb[h * PD + k];
        }
#pragma unroll
        for (int off = 1; off < 8; off <<= 1) {
            sv += __shfl_xor_sync(0xffffffffu, sv, off, 8);
            c1 += __shfl_xor_sync(0xffffffffu, c1, off, 8);
        }
        if (kq == 0) { ssm[h] = sv; c1sm[h] = c1 + bb[h]; }
    }
    __syncthreads();

    int w = tid >> 5, lane = tid & 31;
    int lr = lane >> 2, lc = lane & 3;
    int arow0 = w * 16 + lr;

    float d[4][4];
#pragma unroll
    for (int nc = 0; nc < 4; nc++)
        d[nc][0] = d[nc][1] = d[nc][2] = d[nc][3] = 0.f;

#pragma unroll
    for (int kc = 0; kc < 8; kc++) {
        float af[4];
        af[0] = pt[arow0 * 68 + kc * 8 + lc];
        af[1] = pt[(arow0 + 8) * 68 + kc * 8 + lc];
        af[2] = pt[arow0 * 68 + kc * 8 + lc + 4];
        af[3] = pt[(arow0 + 8) * 68 + kc * 8 + lc + 4];
        unsigned ah[4], al[4];
#pragma unroll
        for (int t = 0; t < 4; t++) {
            CVT_TF32(ah[t], af[t]);
            float res = af[t] - __uint_as_float(ah[t]);
            CVT_TF32(al[t], res);
        }
#pragma unroll
        for (int nc = 0; nc < 4; nc++) {
            float bf0 = wbs[(kc * 8 + lc) * WS + nc * 8 + lr];
            float bf1 = wbs[(kc * 8 + lc + 4) * WS + nc * 8 + lr];
            unsigned bh0, bh1, bl0, bl1;
            CVT_TF32(bh0, bf0);
            CVT_TF32(bh1, bf1);
            float r0 = bf0 - __uint_as_float(bh0);
            float r1 = bf1 - __uint_as_float(bh1);
            CVT_TF32(bl0, r0);
            CVT_TF32(bl1, r1);
            mma_tf32(d[nc][0], d[nc][1], d[nc][2], d[nc][3],
                     ah[0], ah[1], ah[2], ah[3], bh0, bh1);
            mma_tf32(d[nc][0], d[nc][1], d[nc][2], d[nc][3],
                     ah[0], ah[1], ah[2], ah[3], bl0, bl1);
            mma_tf32(d[nc][0], d[nc][1], d[nc][2], d[nc][3],
                     al[0], al[1], al[2], al[3], bh0, bh1);
        }
    }

    float mu0 = mus[arow0],     rs0 = rstds[arow0];
    float mu1 = mus[arow0 + 8], rs1 = rstds[arow0 + 8];
    size_t row = rowbase + arow0;
#pragma unroll
    for (int nc = 0; nc < 4; nc++) {
        int col = nc * 8 + 2 * lc;
        float s0 = ssm[col], s1 = ssm[col + 1];
        float c0 = c1sm[col], c1v = c1sm[col + 1];
        float2 o0, o1;
        o0.x = rs0 * (d[nc][0] - mu0 * s0) + c0;
        o0.y = rs0 * (d[nc][1] - mu0 * s1) + c1v;
        o1.x = rs1 * (d[nc][2] - mu1 * s0) + c0;
        o1.y = rs1 * (d[nc][3] - mu1 * s1) + c1v;
        *(float2*)&g_bias[row * NH + col]       = o0;
        *(float2*)&g_bias[(row + 8) * NH + col] = o1;
    }
}

// ---------------------------------------------------------------------------
// Kernel F: streaming attention + force (R8-proven version).
// ---------------------------------------------------------------------------
__global__ void __launch_bounds__(256, 2) attn_kernel(
    const float* __restrict__ delta, float* __restrict__ out) {
    int c = blockIdx.y;
    int ibase = blockIdx.x * 4;
    int tid = threadIdx.x;
    int w = tid >> 5, h = tid & 31;

    ulonglong2 q[4][4];
#pragma unroll
    for (int ii = 0; ii < 4; ii++) {
        const float* qp = g_q + ((size_t)(c * NN) + ibase + ii) * ED + h * HD;
#pragma unroll
        for (int t = 0; t < 4; t++)
            q[ii][t] = *(const ulonglong2*)(qp + t * 4);
    }

    float l[4]  = {0.f, 0.f, 0.f, 0.f};
    float n0[4] = {0.f, 0.f, 0.f, 0.f};
    float n1[4] = {0.f, 0.f, 0.f, 0.f};
    float n2[4] = {0.f, 0.f, 0.f, 0.f};

    const size_t cb = (size_t)(c * NN) + ibase;
#pragma unroll 2
    for (int j = w; j < NN; j += 8) {
        const float* kp = g_k + ((size_t)(c * NN) + j) * ED + h * HD;
        ulonglong2 k0 = *(const ulonglong2*)(kp + 0);
        ulonglong2 k1 = *(const ulonglong2*)(kp + 4);
        ulonglong2 k2 = *(const ulonglong2*)(kp + 8);
        ulonglong2 k3 = *(const ulonglong2*)(kp + 12);
        float vfv = g_vf[((size_t)(c * NN) + j) * NH + h];
        const float* dp = delta + (cb * NN + j) * 3;
        const float* bp = g_bias + (cb * NN + j) * NH + h;
#pragma unroll
        for (int ii = 0; ii < 4; ii++) {
            unsigned long long a;
            MUL2(a, q[ii][0].x, k0.x);
            FMA2(a, q[ii][0].y, k0.y);
            FMA2(a, q[ii][1].x, k1.x);
            FMA2(a, q[ii][1].y, k1.y);
            FMA2(a, q[ii][2].x, k2.x);
            FMA2(a, q[ii][2].y, k2.y);
            FMA2(a, q[ii][3].x, k3.x);
            FMA2(a, q[ii][3].y, k3.y);
            float lo, hi; UNPACK2(lo, hi, a);
            float z = lo + hi + bp[(size_t)ii * (NN * NH)];
            float we = __expf(z);
            float wv = we * vfv;
            float d0 = dp[ii * (NN * 3) + 0];
            float d1 = dp[ii * (NN * 3) + 1];
            float d2 = dp[ii * (NN * 3) + 2];
            l[ii]  += we;
            n0[ii] += wv * d0;
            n1[ii] += wv * d1;
            n2[ii] += wv * d2;
        }
    }

    __shared__ float ms[8][4][32][4];
#pragma unroll
    for (int ii = 0; ii < 4; ii++)
        *(float4*)&ms[w][ii][h][0] = make_float4(l[ii], n0[ii], n1[ii], n2[ii]);
    __syncthreads();

    if (w < 4) {
        int ii = w;
        float L = 0.f, F0 = 0.f, F1 = 0.f, F2 = 0.f;
#pragma unroll
        for (int ww = 0; ww < 8; ww++) {
            float4 a = *(const float4*)&ms[ww][ii][h][0];
            L += a.x; F0 += a.y; F1 += a.z; F2 += a.w;
        }
        float inv = 1.f / L;
        F0 *= inv; F1 *= inv; F2 *= inv;
#pragma unroll
        for (int off = 16; off; off >>= 1) {
            F0 += __shfl_down_sync(0xffffffffu, F0, off);
            F1 += __shfl_down_sync(0xffffffffu, F1, off);
            F2 += __shfl_down_sync(0xffffffffu, F2, off);
        }
        if (h == 0) {
            float* op = out + ((size_t)(c * NN) + ibase + ii) * 3;
            op[0] = F0; op[1] = F1; op[2] = F2;
        }
    }
}

// ---------------------------------------------------------------------------
// Host launch
// ---------------------------------------------------------------------------
extern "C" void kernel_launch(void* const* d_in, const int* in_sizes, int n_in,
                              void* d_out, int out_size) {
    const float* query = (const float*)d_in[0];
    const float* pair  = (const float*)d_in[1];
    const float* delta = (const float*)d_in[2];
    const float* lnqg  = (const float*)d_in[3];
    const float* lnqb  = (const float*)d_in[4];
    const float* lnpg  = (const float*)d_in[5];
    const float* lnpb  = (const float*)d_in[6];
    const float* Wq    = (const float*)d_in[7];
    const float* Wk    = (const float*)d_in[8];
    const float* Wv    = (const float*)d_in[9];
    const float* Wb    = (const float*)d_in[10];
    const float* bb    = (const float*)d_in[11];
    const float* Wf    = (const float*)d_in[12];
    float* out = (float*)d_out;

    ln_q_kernel<<<NC * NN, 128>>>(query, lnqg, lnqb);

    dim3 gg(ED / 64, (NC * NN) / 128, 3);
    qkv_gemm_tc<<<gg, 256>>>(Wq, Wk, Wv);

    vf_kernel<<<(NC * NN * NH) / 256, 256>>>(Wf);

    bias_kernel<<<(NC * NN * NN) / BM, 256>>>(pair, lnpg, lnpb, Wb, bb);

    attn_kernel<<<dim3(NN / 4, NC), 256>>>(delta, out);
}